// round 3
// baseline (speedup 1.0000x reference)
#include <cuda_runtime.h>
#include <math.h>

#define B_  2
#define S_  2048
#define D_  768
#define H_  12
#define HD_ 64
#define FF_ 3072
#define BS_ (B_ * S_)           // 4096
#define BH_ (B_ * H_)           // 24
#define HEAD_STRIDE (S_ * HD_)  // 131072

// ---------------- scratch (no allocations allowed) ----------------
__device__ float g_q[BS_ * D_];
__device__ float g_k[BS_ * D_];
__device__ float g_v[BS_ * D_];
__device__ float g_ctx[BS_ * D_];
__device__ float g_att[BS_ * D_];
__device__ float g_x1[BS_ * D_];
__device__ float g_ff1[BS_ * FF_];
__device__ float g_ff2[BS_ * D_];

__device__ __forceinline__ float gelu_tanh(float x) {
    const float c = 0.7978845608028654f;  // sqrt(2/pi)
    float t = tanhf(c * (x + 0.044715f * x * x * x));
    return 0.5f * x * (1.0f + t);
}

// ---------------- generic tiled SGEMM ----------------
// C[M,N] = A[M,K] @ Bm[K,N] (+bias) (+rel) (gelu). Batched via blockIdx.z with strides.
// BM=BN=64, BK=16, 256 threads, 4x4 per thread. All dims divisible by tiles here.
template <bool ADD_REL, bool GELU>
__global__ void sgemm_kernel(const float* __restrict__ A, const float* __restrict__ Bm,
                             const float* __restrict__ bias, float* __restrict__ C,
                             int M, int N, int K,
                             long long sA, long long sB, long long sC) {
    __shared__ float As[16][64];
    __shared__ float Bs[16][64];

    const int z = blockIdx.z;
    A += (long long)z * sA;
    Bm += (long long)z * sB;
    C += (long long)z * sC;

    const int tid = threadIdx.x;
    const int tx = tid & 15;       // 0..15
    const int ty = tid >> 4;       // 0..15
    const int rowBase = blockIdx.y * 64;
    const int colBase = blockIdx.x * 64;

    float acc[4][4];
#pragma unroll
    for (int i = 0; i < 4; i++)
#pragma unroll
        for (int j = 0; j < 4; j++) acc[i][j] = 0.0f;

    for (int k0 = 0; k0 < K; k0 += 16) {
        // load A tile [64 x 16] -> As[k][row]
#pragma unroll
        for (int i = 0; i < 4; i++) {
            int idx = tid + i * 256;
            int r = idx >> 4;
            int c = idx & 15;
            As[c][r] = A[(long long)(rowBase + r) * K + (k0 + c)];
        }
        // load B tile [16 x 64] -> Bs[k][col]
#pragma unroll
        for (int i = 0; i < 4; i++) {
            int idx = tid + i * 256;
            int r = idx >> 6;
            int c = idx & 63;
            Bs[r][c] = Bm[(long long)(k0 + r) * N + (colBase + c)];
        }
        __syncthreads();
#pragma unroll
        for (int k = 0; k < 16; k++) {
            float a[4], b[4];
#pragma unroll
            for (int i = 0; i < 4; i++) a[i] = As[k][ty * 4 + i];
#pragma unroll
            for (int j = 0; j < 4; j++) b[j] = Bs[k][tx * 4 + j];
#pragma unroll
            for (int i = 0; i < 4; i++)
#pragma unroll
                for (int j = 0; j < 4; j++) acc[i][j] = fmaf(a[i], b[j], acc[i][j]);
        }
        __syncthreads();
    }

#pragma unroll
    for (int i = 0; i < 4; i++) {
        int row = rowBase + ty * 4 + i;
#pragma unroll
        for (int j = 0; j < 4; j++) {
            int col = colBase + tx * 4 + j;
            float v = acc[i][j];
            if (bias) v += bias[col];
            if (GELU) v = gelu_tanh(v);
            if (ADD_REL) {
                int s = row & (S_ - 1);          // row % 2048
                int p = col - s;
                p = p < -3 ? -3 : (p > 3 ? 3 : p);
                v += (float)p;
            }
            C[(long long)row * N + col] = v;
        }
    }
}

// ---------------- scores = Q @ K^T * scale * mask ----------------
// per (b,h): Q,K contiguous [2048,64]. One block = 64x64 output tile, K=64 single slab.
__global__ void scores_kernel(const float* __restrict__ q, const float* __restrict__ k,
                              const float* __restrict__ mask, float* __restrict__ attn) {
    __shared__ float Qs[64][65];  // Qs[kk][row]
    __shared__ float Ks[64][65];  // Ks[kk][col]

    const int z = blockIdx.z;                 // b*H + h
    const int b = z / H_;
    const float* qb = q + (long long)z * HEAD_STRIDE;
    const float* kb = k + (long long)z * HEAD_STRIDE;
    const float* mb = mask + (long long)b * S_ * S_;
    float* out = attn + (long long)z * S_ * S_;

    const int tid = threadIdx.x;
    const int tx = tid & 15;
    const int ty = tid >> 4;
    const int rowBase = blockIdx.y * 64;
    const int colBase = blockIdx.x * 64;

#pragma unroll
    for (int i = 0; i < 16; i++) {
        int idx = tid + i * 256;
        int r = idx >> 6;    // 0..63
        int c = idx & 63;    // 0..63
        Qs[c][r] = qb[(long long)(rowBase + r) * HD_ + c];
        Ks[c][r] = kb[(long long)(colBase + r) * HD_ + c];
    }
    __syncthreads();

    float acc[4][4];
#pragma unroll
    for (int i = 0; i < 4; i++)
#pragma unroll
        for (int j = 0; j < 4; j++) acc[i][j] = 0.0f;

#pragma unroll 16
    for (int kk = 0; kk < 64; kk++) {
        float a[4], bb[4];
#pragma unroll
        for (int i = 0; i < 4; i++) a[i] = Qs[kk][ty * 4 + i];
#pragma unroll
        for (int j = 0; j < 4; j++) bb[j] = Ks[kk][tx * 4 + j];
#pragma unroll
        for (int i = 0; i < 4; i++)
#pragma unroll
            for (int j = 0; j < 4; j++) acc[i][j] = fmaf(a[i], bb[j], acc[i][j]);
    }

    const float scale = rsqrtf((float)D_);
#pragma unroll
    for (int i = 0; i < 4; i++) {
        int row = rowBase + ty * 4 + i;
#pragma unroll
        for (int j = 0; j < 4; j++) {
            int col = colBase + tx * 4 + j;
            long long o = (long long)row * S_ + col;
            out[o] = acc[i][j] * scale * mb[o];
        }
    }
}

// ---------------- rowwise softmax in place ----------------
// one block per row of attn (B*H*S rows, 2048 cols), 256 threads x 8 cols.
__global__ void softmax_kernel(float* __restrict__ attn) {
    __shared__ float red[8];
    const long long row = blockIdx.x;
    float* p = attn + row * (long long)S_;
    const int t = threadIdx.x;
    const int lane = t & 31;
    const int warp = t >> 5;

    float v[8];
#pragma unroll
    for (int i = 0; i < 8; i++) v[i] = p[t + i * 256];

    // max
    float m = v[0];
#pragma unroll
    for (int i = 1; i < 8; i++) m = fmaxf(m, v[i]);
#pragma unroll
    for (int o = 16; o > 0; o >>= 1) m = fmaxf(m, __shfl_xor_sync(0xffffffffu, m, o));
    if (lane == 0) red[warp] = m;
    __syncthreads();
    m = red[lane & 7];
#pragma unroll
    for (int o = 4; o > 0; o >>= 1) m = fmaxf(m, __shfl_xor_sync(0xffffffffu, m, o));
    __syncthreads();

    // exp + sum
    float s = 0.0f;
#pragma unroll
    for (int i = 0; i < 8; i++) { v[i] = expf(v[i] - m); s += v[i]; }
#pragma unroll
    for (int o = 16; o > 0; o >>= 1) s += __shfl_xor_sync(0xffffffffu, s, o);
    if (lane == 0) red[warp] = s;
    __syncthreads();
    s = red[lane & 7];
#pragma unroll
    for (int o = 4; o > 0; o >>= 1) s += __shfl_xor_sync(0xffffffffu, s, o);

    float inv = 1.0f / s;
#pragma unroll
    for (int i = 0; i < 8; i++) p[t + i * 256] = v[i] * inv;
}

// ---------------- layernorm: out = LN(a + b) * scale + bias ----------------
// one block per row (768 cols), 256 threads x 3.
__global__ void ln_kernel(const float* __restrict__ a, const float* __restrict__ bres,
                          const float* __restrict__ scale, const float* __restrict__ bias,
                          float* __restrict__ out) {
    __shared__ float red[8];
    const long long row = blockIdx.x;
    const int t = threadIdx.x;
    const int lane = t & 31;
    const int warp = t >> 5;

    float v[3];
#pragma unroll
    for (int i = 0; i < 3; i++) {
        long long idx = row * D_ + t + i * 256;
        v[i] = a[idx] + bres[idx];
    }

    float s = v[0] + v[1] + v[2];
#pragma unroll
    for (int o = 16; o > 0; o >>= 1) s += __shfl_xor_sync(0xffffffffu, s, o);
    if (lane == 0) red[warp] = s;
    __syncthreads();
    s = red[lane & 7];
#pragma unroll
    for (int o = 4; o > 0; o >>= 1) s += __shfl_xor_sync(0xffffffffu, s, o);
    const float mean = s * (1.0f / D_);
    __syncthreads();

    float q = 0.0f;
#pragma unroll
    for (int i = 0; i < 3; i++) { float d = v[i] - mean; q += d * d; }
#pragma unroll
    for (int o = 16; o > 0; o >>= 1) q += __shfl_xor_sync(0xffffffffu, q, o);
    if (lane == 0) red[warp] = q;
    __syncthreads();
    q = red[lane & 7];
#pragma unroll
    for (int o = 4; o > 0; o >>= 1) q += __shfl_xor_sync(0xffffffffu, q, o);
    const float var = q * (1.0f / D_);
    const float rstd = rsqrtf(var + 1e-6f);

#pragma unroll
    for (int i = 0; i < 3; i++) {
        int c = t + i * 256;
        out[row * D_ + c] = (v[i] - mean) * rstd * scale[c] + bias[c];
    }
}

// ---------------- launch ----------------
extern "C" void kernel_launch(void* const* d_in, const int* in_sizes, int n_in,
                              void* d_out, int out_size) {
    const float* x    = (const float*)d_in[0];
    const float* mask = (const float*)d_in[1];
    const float* Wq   = (const float*)d_in[2];
    const float* bq   = (const float*)d_in[3];
    const float* Wk   = (const float*)d_in[4];
    const float* bk   = (const float*)d_in[5];
    const float* Wv   = (const float*)d_in[6];
    const float* bv   = (const float*)d_in[7];
    const float* Wo   = (const float*)d_in[8];
    const float* bo   = (const float*)d_in[9];
    const float* W1   = (const float*)d_in[10];
    const float* b1   = (const float*)d_in[11];
    const float* W2   = (const float*)d_in[12];
    const float* b2   = (const float*)d_in[13];
    const float* ln1s = (const float*)d_in[14];
    const float* ln1b = (const float*)d_in[15];
    const float* ln2s = (const float*)d_in[16];
    const float* ln2b = (const float*)d_in[17];

    float* out_x2   = (float*)d_out;                         // B*S*D
    float* out_attn = (float*)d_out + (long long)BS_ * D_;   // B*H*S*S

    float* q   = nullptr; cudaGetSymbolAddress((void**)&q,   g_q);
    float* k   = nullptr; cudaGetSymbolAddress((void**)&k,   g_k);
    float* v   = nullptr; cudaGetSymbolAddress((void**)&v,   g_v);
    float* ctx = nullptr; cudaGetSymbolAddress((void**)&ctx, g_ctx);
    float* att = nullptr; cudaGetSymbolAddress((void**)&att, g_att);
    float* x1  = nullptr; cudaGetSymbolAddress((void**)&x1,  g_x1);
    float* f1  = nullptr; cudaGetSymbolAddress((void**)&f1,  g_ff1);
    float* f2  = nullptr; cudaGetSymbolAddress((void**)&f2,  g_ff2);

    dim3 blk(256);

    // QKV projections (+rel bias on q,v)
    dim3 gq(D_ / 64, BS_ / 64, 1);
    sgemm_kernel<true,  false><<<gq, blk>>>(x, Wq, bq, q, BS_, D_, D_, 0, 0, 0);
    sgemm_kernel<false, false><<<gq, blk>>>(x, Wk, bk, k, BS_, D_, D_, 0, 0, 0);
    sgemm_kernel<true,  false><<<gq, blk>>>(x, Wv, bv, v, BS_, D_, D_, 0, 0, 0);

    // scores -> out_attn (scaled, masked)
    dim3 gs(S_ / 64, S_ / 64, BH_);
    scores_kernel<<<gs, blk>>>(q, k, mask, out_attn);

    // softmax rows
    softmax_kernel<<<BH_ * S_, blk>>>(out_attn);

    // ctx = attn @ V  (batched over heads)
    dim3 gc(1, S_ / 64, BH_);
    sgemm_kernel<false, false><<<gc, blk>>>(out_attn, v, nullptr, ctx,
                                            S_, HD_, S_,
                                            (long long)S_ * S_, HEAD_STRIDE, HEAD_STRIDE);

    // attended = ctx @ Wo + bo
    sgemm_kernel<false, false><<<gq, blk>>>(ctx, Wo, bo, att, BS_, D_, D_, 0, 0, 0);

    // x1 = LN(att + x)
    ln_kernel<<<BS_, blk>>>(att, x, ln1s, ln1b, x1);

    // ff1 = gelu(x1 @ W1 + b1)
    dim3 g1(FF_ / 64, BS_ / 64, 1);
    sgemm_kernel<false, true><<<g1, blk>>>(x1, W1, b1, f1, BS_, FF_, D_, 0, 0, 0);

    // ff2 = ff1 @ W2 + b2
    sgemm_kernel<false, false><<<gq, blk>>>(f1, W2, b2, f2, BS_, D_, FF_, 0, 0, 0);

    // x2 = LN(ff2 + x1) -> out
    ln_kernel<<<BS_, blk>>>(f2, x1, ln2s, ln2b, out_x2);
}

// round 8
// speedup vs baseline: 2.4289x; 2.4289x over previous
#include <cuda_runtime.h>
#include <cuda_bf16.h>
#include <math.h>

#define B_  2
#define S_  2048
#define D_  768
#define H_  12
#define HD_ 64
#define FF_ 3072
#define BS_ (B_ * S_)           // 4096
#define BH_ (B_ * H_)           // 24
#define HEAD_STRIDE (S_ * HD_)  // 131072

// ---------------- scratch (no allocations allowed) ----------------
__device__ float g_q[BS_ * D_];
__device__ float g_k[BS_ * D_];
__device__ float g_v[BS_ * D_];
__device__ float g_ctx[BS_ * D_];
__device__ float g_att[BS_ * D_];
__device__ float g_x1[BS_ * D_];
__device__ float g_ff1[BS_ * FF_];
__device__ float g_ff2[BS_ * D_];

__device__ __forceinline__ float gelu_tanh(float x) {
    const float c = 0.7978845608028654f;  // sqrt(2/pi)
    float t = tanhf(c * (x + 0.044715f * x * x * x));
    return 0.5f * x * (1.0f + t);
}

// ---------------- ptx helpers ----------------
__device__ __forceinline__ unsigned smem_u32(const void* p) {
    return (unsigned)__cvta_generic_to_shared(p);
}
__device__ __forceinline__ void cp_async16(void* s, const void* g) {
    asm volatile("cp.async.cg.shared.global [%0], [%1], 16;\n"
                 :: "r"(smem_u32(s)), "l"(g));
}
__device__ __forceinline__ void cp_commit() {
    asm volatile("cp.async.commit_group;\n");
}
template <int N>
__device__ __forceinline__ void cp_wait() {
    asm volatile("cp.async.wait_group %0;\n" :: "n"(N));
}

// bf16x3 split: x = hi + lo, hi/lo bf16 (round-to-nearest). Packs pairs.
__device__ __forceinline__ unsigned pack2(__nv_bfloat16 a, __nv_bfloat16 b) {
    __nv_bfloat162 t = __halves2bfloat162(a, b);
    return *reinterpret_cast<unsigned*>(&t);
}
__device__ __forceinline__ void split2(float x0, float x1, unsigned& hi, unsigned& lo) {
    __nv_bfloat16 h0 = __float2bfloat16(x0);
    __nv_bfloat16 h1 = __float2bfloat16(x1);
    __nv_bfloat16 l0 = __float2bfloat16(x0 - __bfloat162float(h0));
    __nv_bfloat16 l1 = __float2bfloat16(x1 - __bfloat162float(h1));
    hi = pack2(h0, h1);
    lo = pack2(l0, l1);
}

// D += A @ B, m16n8k16 bf16, fp32 accumulate
__device__ __forceinline__ void mma_bf16(float* d, const unsigned* a, const unsigned* b) {
    asm volatile(
        "mma.sync.aligned.m16n8k16.row.col.f32.bf16.bf16.f32 "
        "{%0,%1,%2,%3}, {%4,%5,%6,%7}, {%8,%9}, {%0,%1,%2,%3};\n"
        : "+f"(d[0]), "+f"(d[1]), "+f"(d[2]), "+f"(d[3])
        : "r"(a[0]), "r"(a[1]), "r"(a[2]), "r"(a[3]),
          "r"(b[0]), "r"(b[1]));
}

// ---------------- generic bf16x3 tensor-core GEMM ----------------
// C[M,N] = A[M,K] @ B[K,N] (+bias) (+rel) (gelu), batched via blockIdx.z strides.
// BM=128, BN=64, BK=16, 256 threads (8 warps, 4x2 of 32x32 warp tiles).
// fp32 smem (cp.async double-buffered); fragments split to bf16 hi/lo in regs;
// per tile 3 MMAs: hi*hi + hi*lo + lo*hi (~2^-18 effective precision).
template <bool REL, bool GELU>
__global__ __launch_bounds__(256) void bf16x3_gemm(
    const float* __restrict__ A, const float* __restrict__ Bm,
    const float* __restrict__ bias, float* __restrict__ C,
    int M, int N, int K, long long sA, long long sB, long long sC)
{
    __shared__ float As[2][128][20];
    __shared__ float Bs[2][16][76];

    const int z = blockIdx.z;
    A += (long long)z * sA;
    Bm += (long long)z * sB;
    C += (long long)z * sC;

    const int tid = threadIdx.x;
    const int wid = tid >> 5, lane = tid & 31;
    const int gid = lane >> 2, tig = lane & 3;
    const int wm = (wid >> 1) * 32;       // warp row offset (0..96)
    const int wn = (wid & 1) * 32;        // warp col offset (0/32)
    const int rowBase = blockIdx.y * 128;
    const int colBase = blockIdx.x * 64;

    // A tile: 128x16 floats = 512 float4, 2 per thread
    const int a_row0 = (2 * tid) >> 2,     a_kq0 = (2 * tid) & 3;
    const int a_row1 = (2 * tid + 1) >> 2, a_kq1 = (2 * tid + 1) & 3;
    // B tile: 16x64 floats = 256 float4, 1 per thread
    const int b_row = tid >> 4, b_nq = tid & 15;

    float acc[2][4][4];
#pragma unroll
    for (int mi = 0; mi < 2; mi++)
#pragma unroll
        for (int ni = 0; ni < 4; ni++)
#pragma unroll
            for (int j = 0; j < 4; j++) acc[mi][ni][j] = 0.0f;

    auto loadTile = [&](int c, int st) {
        const int k0 = c << 4;
        cp_async16(&As[st][a_row0][a_kq0 * 4],
                   A + (long long)(rowBase + a_row0) * K + k0 + a_kq0 * 4);
        cp_async16(&As[st][a_row1][a_kq1 * 4],
                   A + (long long)(rowBase + a_row1) * K + k0 + a_kq1 * 4);
        cp_async16(&Bs[st][b_row][b_nq * 4],
                   Bm + (long long)(k0 + b_row) * N + colBase + b_nq * 4);
    };

    const int nc = K >> 4;
    loadTile(0, 0);
    cp_commit();

    for (int c = 0; c < nc; c++) {
        const int cur = c & 1;
        if (c + 1 < nc) {
            loadTile(c + 1, cur ^ 1);
            cp_commit();
            cp_wait<1>();
        } else {
            cp_wait<0>();
        }
        __syncthreads();

        // ---- fragment load + bf16x3 split (one k16 slice per tile) ----
        unsigned ahi[2][4], alo[2][4];
#pragma unroll
        for (int mi = 0; mi < 2; mi++) {
            const int r0 = wm + mi * 16 + gid;
            const float2 x0 = *reinterpret_cast<const float2*>(&As[cur][r0    ][2 * tig]);
            const float2 x1 = *reinterpret_cast<const float2*>(&As[cur][r0 + 8][2 * tig]);
            const float2 x2 = *reinterpret_cast<const float2*>(&As[cur][r0    ][2 * tig + 8]);
            const float2 x3 = *reinterpret_cast<const float2*>(&As[cur][r0 + 8][2 * tig + 8]);
            split2(x0.x, x0.y, ahi[mi][0], alo[mi][0]);
            split2(x1.x, x1.y, ahi[mi][1], alo[mi][1]);
            split2(x2.x, x2.y, ahi[mi][2], alo[mi][2]);
            split2(x3.x, x3.y, ahi[mi][3], alo[mi][3]);
        }
        unsigned bhi[4][2], blo[4][2];
#pragma unroll
        for (int ni = 0; ni < 4; ni++) {
            const int n = wn + ni * 8 + gid;
            const float y0 = Bs[cur][2 * tig    ][n];
            const float y1 = Bs[cur][2 * tig + 1][n];
            const float y2 = Bs[cur][2 * tig + 8][n];
            const float y3 = Bs[cur][2 * tig + 9][n];
            split2(y0, y1, bhi[ni][0], blo[ni][0]);
            split2(y2, y3, bhi[ni][1], blo[ni][1]);
        }
#pragma unroll
        for (int mi = 0; mi < 2; mi++)
#pragma unroll
            for (int ni = 0; ni < 4; ni++) {
                mma_bf16(acc[mi][ni], ahi[mi], bhi[ni]);
                mma_bf16(acc[mi][ni], ahi[mi], blo[ni]);
                mma_bf16(acc[mi][ni], alo[mi], bhi[ni]);
            }
        __syncthreads();
    }

    // epilogue: c0,c1 = (row, 2t/2t+1), c2,c3 = (row+8, ...)
#pragma unroll
    for (int mi = 0; mi < 2; mi++) {
#pragma unroll
        for (int i = 0; i < 2; i++) {
            const int r = rowBase + wm + mi * 16 + gid + i * 8;
#pragma unroll
            for (int ni = 0; ni < 4; ni++) {
                const int c0 = colBase + wn + ni * 8 + 2 * tig;
                float v0 = acc[mi][ni][i * 2 + 0];
                float v1 = acc[mi][ni][i * 2 + 1];
                if (bias) { v0 += bias[c0]; v1 += bias[c0 + 1]; }
                if (GELU) { v0 = gelu_tanh(v0); v1 = gelu_tanh(v1); }
                if (REL) {
                    const int s = r & (S_ - 1);
                    int p0 = c0 - s;     p0 = p0 < -3 ? -3 : (p0 > 3 ? 3 : p0);
                    int p1 = c0 + 1 - s; p1 = p1 < -3 ? -3 : (p1 > 3 ? 3 : p1);
                    v0 += (float)p0; v1 += (float)p1;
                }
                *reinterpret_cast<float2*>(&C[(long long)r * N + c0]) =
                    make_float2(v0, v1);
            }
        }
    }
}

// ---------------- scores = (Q @ K^T) * scale * mask, bf16x3 ----------------
// Per (b,h): Q,K contiguous [2048,64]. BM=64, BN=64, full K=64 in smem.
// Qs/Ks natural [seq][feat] layout, stride 72 -> conflict-free float2 frag reads.
__global__ __launch_bounds__(256) void scores_bf16x3(
    const float* __restrict__ q, const float* __restrict__ k,
    const float* __restrict__ mask, float* __restrict__ attn)
{
    __shared__ float Qs[64][72];
    __shared__ float Ks[64][72];

    const int z = blockIdx.z;  // b*H + h
    const int b = z / H_;
    const float* qb = q + (long long)z * HEAD_STRIDE;
    const float* kb = k + (long long)z * HEAD_STRIDE;
    const float* mb = mask + (long long)b * S_ * S_;
    float* out = attn + (long long)z * S_ * S_;

    const int tid = threadIdx.x;
    const int wid = tid >> 5, lane = tid & 31;
    const int gid = lane >> 2, tig = lane & 3;
    const int wm = (wid >> 1) * 16;   // 4 warp-rows of 16
    const int wn = (wid & 1) * 32;    // 2 warp-cols of 32
    const int rowBase = blockIdx.y * 64;
    const int colBase = blockIdx.x * 64;

    // each tile: 64 rows x 16 float4 = 1024 float4 -> 4 per thread
#pragma unroll
    for (int i = 0; i < 4; i++) {
        const int idx = tid + i * 256;
        const int r = idx >> 4, kq = idx & 15;
        cp_async16(&Qs[r][kq * 4], qb + (long long)(rowBase + r) * HD_ + kq * 4);
        cp_async16(&Ks[r][kq * 4], kb + (long long)(colBase + r) * HD_ + kq * 4);
    }
    cp_commit();
    cp_wait<0>();
    __syncthreads();

    float acc[4][4];
#pragma unroll
    for (int ni = 0; ni < 4; ni++)
#pragma unroll
        for (int j = 0; j < 4; j++) acc[ni][j] = 0.0f;

#pragma unroll
    for (int ks = 0; ks < 4; ks++) {
        const int kb16 = ks * 16;
        unsigned ahi[4], alo[4], bhi[4][2], blo[4][2];
        {
            const int r = wm + gid;
            const float2 x0 = *reinterpret_cast<const float2*>(&Qs[r    ][kb16 + 2 * tig]);
            const float2 x1 = *reinterpret_cast<const float2*>(&Qs[r + 8][kb16 + 2 * tig]);
            const float2 x2 = *reinterpret_cast<const float2*>(&Qs[r    ][kb16 + 2 * tig + 8]);
            const float2 x3 = *reinterpret_cast<const float2*>(&Qs[r + 8][kb16 + 2 * tig + 8]);
            split2(x0.x, x0.y, ahi[0], alo[0]);
            split2(x1.x, x1.y, ahi[1], alo[1]);
            split2(x2.x, x2.y, ahi[2], alo[2]);
            split2(x3.x, x3.y, ahi[3], alo[3]);
        }
#pragma unroll
        for (int ni = 0; ni < 4; ni++) {
            const int n = wn + ni * 8 + gid;
            const float2 y0 = *reinterpret_cast<const float2*>(&Ks[n][kb16 + 2 * tig]);
            const float2 y1 = *reinterpret_cast<const float2*>(&Ks[n][kb16 + 2 * tig + 8]);
            split2(y0.x, y0.y, bhi[ni][0], blo[ni][0]);
            split2(y1.x, y1.y, bhi[ni][1], blo[ni][1]);
        }
#pragma unroll
        for (int ni = 0; ni < 4; ni++) {
            mma_bf16(acc[ni], ahi, bhi[ni]);
            mma_bf16(acc[ni], ahi, blo[ni]);
            mma_bf16(acc[ni], alo, bhi[ni]);
        }
    }

    const float scale = rsqrtf((float)D_);
#pragma unroll
    for (int i = 0; i < 2; i++) {
        const int r = rowBase + wm + gid + i * 8;
        const long long ro = (long long)r * S_;
#pragma unroll
        for (int ni = 0; ni < 4; ni++) {
            const int c0 = colBase + wn + ni * 8 + 2 * tig;
            const float2 m2 = *reinterpret_cast<const float2*>(&mb[ro + c0]);
            *reinterpret_cast<float2*>(&out[ro + c0]) =
                make_float2(acc[ni][i * 2 + 0] * scale * m2.x,
                            acc[ni][i * 2 + 1] * scale * m2.y);
        }
    }
}

// ---------------- rowwise softmax in place ----------------
__global__ void softmax_kernel(float* __restrict__ attn) {
    __shared__ float red[8];
    const long long row = blockIdx.x;
    float* p = attn + row * (long long)S_;
    const int t = threadIdx.x;
    const int lane = t & 31;
    const int warp = t >> 5;

    float v[8];
#pragma unroll
    for (int i = 0; i < 8; i++) v[i] = p[t + i * 256];

    float m = v[0];
#pragma unroll
    for (int i = 1; i < 8; i++) m = fmaxf(m, v[i]);
#pragma unroll
    for (int o = 16; o > 0; o >>= 1) m = fmaxf(m, __shfl_xor_sync(0xffffffffu, m, o));
    if (lane == 0) red[warp] = m;
    __syncthreads();
    m = red[lane & 7];
#pragma unroll
    for (int o = 4; o > 0; o >>= 1) m = fmaxf(m, __shfl_xor_sync(0xffffffffu, m, o));
    __syncthreads();

    float s = 0.0f;
#pragma unroll
    for (int i = 0; i < 8; i++) { v[i] = expf(v[i] - m); s += v[i]; }
#pragma unroll
    for (int o = 16; o > 0; o >>= 1) s += __shfl_xor_sync(0xffffffffu, s, o);
    if (lane == 0) red[warp] = s;
    __syncthreads();
    s = red[lane & 7];
#pragma unroll
    for (int o = 4; o > 0; o >>= 1) s += __shfl_xor_sync(0xffffffffu, s, o);

    const float inv = 1.0f / s;
#pragma unroll
    for (int i = 0; i < 8; i++) p[t + i * 256] = v[i] * inv;
}

// ---------------- layernorm: out = LN(a + b) * scale + bias ----------------
__global__ void ln_kernel(const float* __restrict__ a, const float* __restrict__ bres,
                          const float* __restrict__ scale, const float* __restrict__ bias,
                          float* __restrict__ out) {
    __shared__ float red[8];
    const long long row = blockIdx.x;
    const int t = threadIdx.x;
    const int lane = t & 31;
    const int warp = t >> 5;

    float v[3];
#pragma unroll
    for (int i = 0; i < 3; i++) {
        long long idx = row * D_ + t + i * 256;
        v[i] = a[idx] + bres[idx];
    }

    float s = v[0] + v[1] + v[2];
#pragma unroll
    for (int o = 16; o > 0; o >>= 1) s += __shfl_xor_sync(0xffffffffu, s, o);
    if (lane == 0) red[warp] = s;
    __syncthreads();
    s = red[lane & 7];
#pragma unroll
    for (int o = 4; o > 0; o >>= 1) s += __shfl_xor_sync(0xffffffffu, s, o);
    const float mean = s * (1.0f / D_);
    __syncthreads();

    float q = 0.0f;
#pragma unroll
    for (int i = 0; i < 3; i++) { float d = v[i] - mean; q += d * d; }
#pragma unroll
    for (int o = 16; o > 0; o >>= 1) q += __shfl_xor_sync(0xffffffffu, q, o);
    if (lane == 0) red[warp] = q;
    __syncthreads();
    q = red[lane & 7];
#pragma unroll
    for (int o = 4; o > 0; o >>= 1) q += __shfl_xor_sync(0xffffffffu, q, o);
    const float var = q * (1.0f / D_);
    const float rstd = rsqrtf(var + 1e-6f);

#pragma unroll
    for (int i = 0; i < 3; i++) {
        int c = t + i * 256;
        out[row * D_ + c] = (v[i] - mean) * rstd * scale[c] + bias[c];
    }
}

// ---------------- launch ----------------
extern "C" void kernel_launch(void* const* d_in, const int* in_sizes, int n_in,
                              void* d_out, int out_size) {
    const float* x    = (const float*)d_in[0];
    const float* mask = (const float*)d_in[1];
    const float* Wq   = (const float*)d_in[2];
    const float* bq   = (const float*)d_in[3];
    const float* Wk   = (const float*)d_in[4];
    const float* bk   = (const float*)d_in[5];
    const float* Wv   = (const float*)d_in[6];
    const float* bv   = (const float*)d_in[7];
    const float* Wo   = (const float*)d_in[8];
    const float* bo   = (const float*)d_in[9];
    const float* W1   = (const float*)d_in[10];
    const float* b1   = (const float*)d_in[11];
    const float* W2   = (const float*)d_in[12];
    const float* b2   = (const float*)d_in[13];
    const float* ln1s = (const float*)d_in[14];
    const float* ln1b = (const float*)d_in[15];
    const float* ln2s = (const float*)d_in[16];
    const float* ln2b = (const float*)d_in[17];

    float* out_x2   = (float*)d_out;                         // B*S*D
    float* out_attn = (float*)d_out + (long long)BS_ * D_;   // B*H*S*S

    float* q   = nullptr; cudaGetSymbolAddress((void**)&q,   g_q);
    float* k   = nullptr; cudaGetSymbolAddress((void**)&k,   g_k);
    float* v   = nullptr; cudaGetSymbolAddress((void**)&v,   g_v);
    float* ctx = nullptr; cudaGetSymbolAddress((void**)&ctx, g_ctx);
    float* att = nullptr; cudaGetSymbolAddress((void**)&att, g_att);
    float* x1  = nullptr; cudaGetSymbolAddress((void**)&x1,  g_x1);
    float* f1  = nullptr; cudaGetSymbolAddress((void**)&f1,  g_ff1);
    float* f2  = nullptr; cudaGetSymbolAddress((void**)&f2,  g_ff2);

    dim3 blk(256);

    // QKV projections (+rel bias on q,v): [4096,768] @ [768,768]
    dim3 gp(D_ / 64, BS_ / 128, 1);
    bf16x3_gemm<true,  false><<<gp, blk>>>(x, Wq, bq, q, BS_, D_, D_, 0, 0, 0);
    bf16x3_gemm<false, false><<<gp, blk>>>(x, Wk, bk, k, BS_, D_, D_, 0, 0, 0);
    bf16x3_gemm<true,  false><<<gp, blk>>>(x, Wv, bv, v, BS_, D_, D_, 0, 0, 0);

    // scores -> out_attn (scaled, masked)
    dim3 gs(S_ / 64, S_ / 64, BH_);
    scores_bf16x3<<<gs, blk>>>(q, k, mask, out_attn);

    // softmax rows
    softmax_kernel<<<BH_ * S_, blk>>>(out_attn);

    // ctx = attn @ V (batched over heads): [2048,2048] @ [2048,64]
    dim3 gc(1, S_ / 128, BH_);
    bf16x3_gemm<false, false><<<gc, blk>>>(out_attn, v, nullptr, ctx,
                                           S_, HD_, S_,
                                           (long long)S_ * S_, HEAD_STRIDE, HEAD_STRIDE);

    // attended = ctx @ Wo + bo
    bf16x3_gemm<false, false><<<gp, blk>>>(ctx, Wo, bo, att, BS_, D_, D_, 0, 0, 0);

    // x1 = LN(att + x)
    ln_kernel<<<BS_, blk>>>(att, x, ln1s, ln1b, x1);

    // ff1 = gelu(x1 @ W1 + b1): [4096,768] @ [768,3072]
    dim3 g1(FF_ / 64, BS_ / 128, 1);
    bf16x3_gemm<false, true><<<g1, blk>>>(x1, W1, b1, f1, BS_, FF_, D_, 0, 0, 0);

    // ff2 = ff1 @ W2 + b2: [4096,3072] @ [3072,768]
    bf16x3_gemm<false, false><<<gp, blk>>>(f1, W2, b2, f2, BS_, D_, FF_, 0, 0, 0);

    // x2 = LN(ff2 + x1) -> out
    ln_kernel<<<BS_, blk>>>(f2, x1, ln2s, ln2b, out_x2);
}